// round 4
// baseline (speedup 1.0000x reference)
#include <cuda_runtime.h>

#define NCELL   65536
#define TSTEPS  365
#define HID     64
#define G3      192
#define CELLS_PB 128
#define THREADS  256

// ---------- packed f32x2 helpers (Blackwell FFMA2, PTX-only) ----------
__device__ __forceinline__ unsigned long long pk2(float a, float b) {
    unsigned long long r;
    asm("mov.b64 %0, {%1, %2};"
        : "=l"(r) : "r"(__float_as_uint(a)), "r"(__float_as_uint(b)));
    return r;
}
__device__ __forceinline__ void fma2(unsigned long long& d,
                                     unsigned long long a,
                                     unsigned long long b) {
    asm("fma.rn.f32x2 %0, %1, %2, %0;" : "+l"(d) : "l"(a), "l"(b));
}
__device__ __forceinline__ float2 up2(unsigned long long v) {
    unsigned lo, hi;
    asm("mov.b64 {%0, %1}, %2;" : "=r"(lo), "=r"(hi) : "l"(v));
    return make_float2(__uint_as_float(lo), __uint_as_float(hi));
}
__device__ __forceinline__ float sigm(float x) {
    return 1.0f / (1.0f + __expf(-x));
}

// ---------- half mat-vec for one gate ----------
// Wt[j*192 + k] = W_hh[k*64 + j]  (transposed, gate-contiguous in k)
// This thread covers k = 8*i + 4*slice + {0..3}, i = 0..7  (32 outputs)
// acc[2i]   packs (8i+4s+0, 8i+4s+1), acc[2i+1] packs (+2,+3)
template <int G>
__device__ __forceinline__ void mv_half(const float* __restrict__ Wt,
                                        const float* __restrict__ hcol,
                                        int slice,
                                        unsigned long long acc[16]) {
#pragma unroll
    for (int m = 0; m < 16; ++m) acc[m] = 0ull;
#pragma unroll 4
    for (int j = 0; j < HID; ++j) {
        float hj = hcol[j * CELLS_PB];
        unsigned long long h2 = pk2(hj, hj);
        const ulonglong2* w =
            reinterpret_cast<const ulonglong2*>(Wt + j * G3 + G) + slice;
#pragma unroll
        for (int i = 0; i < 8; ++i) {
            ulonglong2 wv = w[2 * i];       // 4 consecutive k-weights (LDS.128)
            fma2(acc[2 * i + 0], wv.x, h2);
            fma2(acc[2 * i + 1], wv.y, h2);
        }
    }
}

// dynamic smem (floats):
//   Wt   [64*192] = 12288
//   h_sh [64*128] =  8192   layout [k][cell]
//   wpk  [192*4]  =   768   per-k float4: (wih0, wih1, bias, extra)
//                           extra = out_w[k-64]  for k in [64,128)
//                                 = bias_n[k-128] for k in [128,192)
#define SM_FLOATS (12288 + 8192 + 768)

__global__ void __launch_bounds__(THREADS, 2)
gru_persistent_kernel(const float* __restrict__ precip,
                      const float* __restrict__ temp,
                      const float* __restrict__ w_ih,
                      const float* __restrict__ w_hh,
                      const float* __restrict__ bias,
                      const float* __restrict__ bias_n,
                      const float* __restrict__ out_w,
                      const float* __restrict__ out_b,
                      const float* __restrict__ init_h,
                      float* __restrict__ out) {
    extern __shared__ float sm[];
    float*  Wt   = sm;                 // 12288
    float*  h_sh = Wt + 12288;         // 8192
    float4* wpk  = reinterpret_cast<float4*>(h_sh + 8192);  // 192 float4

    const int tid   = threadIdx.x;
    const int ci    = tid >> 1;        // cell index in block (0..127)
    const int slice = tid & 1;         // which half of the outputs
    const int cell  = blockIdx.x * CELLS_PB + ci;

    // ---- stage weights (transpose W_hh) ----
    for (int i = tid; i < G3 * HID; i += THREADS) {
        int k = i >> 6, j = i & 63;
        Wt[j * G3 + k] = w_hh[i];
    }
    for (int k = tid; k < G3; k += THREADS) {
        float ex = 0.0f;
        if (k >= 128)      ex = bias_n[k - 128];
        else if (k >= 64)  ex = out_w[k - 64];
        wpk[k] = make_float4(w_ih[2 * k], w_ih[2 * k + 1], bias[k], ex);
    }
    for (int i = tid; i < HID * CELLS_PB; i += THREADS)
        h_sh[i] = init_h[i >> 7];      // broadcast init_h[j] to all cells
    __syncthreads();

    const float ob = out_b[0];
    const float* hcol = h_sh + ci;

    float R[32];                       // reset, then reused as "new"
    unsigned long long acc[16];

    for (int t = 0; t < TSTEPS; ++t) {
        const int base = t * NCELL + cell;
        const float p  = precip[base];
        const float tm = temp[base];

        // ---- pass 1: reset gate ----
        mv_half<0>(Wt, hcol, slice, acc);
#pragma unroll
        for (int m = 0; m < 16; ++m) {
            float2 hr = up2(acc[m]);
            int kb = 8 * (m >> 1) + 4 * slice + 2 * (m & 1);
            float4 c0 = wpk[kb], c1 = wpk[kb + 1];
            float ig0 = fmaf(c0.x, p, fmaf(c0.y, tm, c0.z));
            float ig1 = fmaf(c1.x, p, fmaf(c1.y, tm, c1.z));
            R[2 * m + 0] = sigm(ig0 + hr.x);
            R[2 * m + 1] = sigm(ig1 + hr.y);
        }

        // ---- pass 2: candidate: new = tanh(in + r*(hn + bias_n)) ----
        mv_half<128>(Wt, hcol, slice, acc);
#pragma unroll
        for (int m = 0; m < 16; ++m) {
            float2 hn = up2(acc[m]);
            int kb = 8 * (m >> 1) + 4 * slice + 2 * (m & 1);
            float4 c0 = wpk[128 + kb], c1 = wpk[128 + kb + 1];
            float ig0 = fmaf(c0.x, p, fmaf(c0.y, tm, c0.z));
            float ig1 = fmaf(c1.x, p, fmaf(c1.y, tm, c1.z));
            R[2 * m + 0] = tanhf(fmaf(R[2 * m + 0], hn.x + c0.w, ig0));
            R[2 * m + 1] = tanhf(fmaf(R[2 * m + 1], hn.y + c1.w, ig1));
        }

        // ---- pass 3: update gate + state update + output ----
        mv_half<64>(Wt, hcol, slice, acc);
        float y = (slice == 0) ? ob : 0.0f;
#pragma unroll
        for (int m = 0; m < 16; ++m) {
            float2 hz = up2(acc[m]);
            int kb = 8 * (m >> 1) + 4 * slice + 2 * (m & 1);
            float4 c0 = wpk[64 + kb], c1 = wpk[64 + kb + 1];
            float ig0 = fmaf(c0.x, p, fmaf(c0.y, tm, c0.z));
            float ig1 = fmaf(c1.x, p, fmaf(c1.y, tm, c1.z));
            float u0 = sigm(ig0 + hz.x);
            float u1 = sigm(ig1 + hz.y);
            float hold0 = h_sh[kb * CELLS_PB + ci];
            float hold1 = h_sh[(kb + 1) * CELLS_PB + ci];
            float n0 = R[2 * m + 0], n1 = R[2 * m + 1];
            float hn0 = fmaf(u0, hold0 - n0, n0);   // new + u*(h - new)
            float hn1 = fmaf(u1, hold1 - n1, n1);
            h_sh[kb * CELLS_PB + ci]       = hn0;
            h_sh[(kb + 1) * CELLS_PB + ci] = hn1;
            y = fmaf(c0.w, hn0, y);                 // c0.w = out_w[kb]
            y = fmaf(c1.w, hn1, y);
        }

        // combine the two slices' partial dot products
        y += __shfl_xor_sync(0xFFFFFFFFu, y, 1);
        if (slice == 0) out[base] = y;              // smb[t, cell]

        __syncwarp();   // pair lane's h writes visible before next step's reads
    }

    // ---- final hidden state: out[T*N + cell*64 + k] for this thread's ks ----
    float* fo = out + (long long)TSTEPS * NCELL + (long long)cell * HID;
#pragma unroll
    for (int l = 0; l < 32; ++l) {
        int k = 8 * (l >> 2) + 4 * slice + (l & 3);
        fo[k] = h_sh[k * CELLS_PB + ci];
    }
}

extern "C" void kernel_launch(void* const* d_in, const int* in_sizes, int n_in,
                              void* d_out, int out_size) {
    const float* precip = (const float*)d_in[0];
    const float* temp   = (const float*)d_in[1];
    const float* w_ih   = (const float*)d_in[2];
    const float* w_hh   = (const float*)d_in[3];
    const float* bias   = (const float*)d_in[4];
    const float* bias_n = (const float*)d_in[5];
    const float* out_w  = (const float*)d_in[6];
    const float* out_b  = (const float*)d_in[7];
    const float* init_h = (const float*)d_in[8];
    float* out = (float*)d_out;

    const int smem_bytes = SM_FLOATS * sizeof(float);  // 84992 B
    cudaFuncSetAttribute(gru_persistent_kernel,
                         cudaFuncAttributeMaxDynamicSharedMemorySize,
                         smem_bytes);

    gru_persistent_kernel<<<NCELL / CELLS_PB, THREADS, smem_bytes>>>(
        precip, temp, w_ih, w_hh, bias, bias_n, out_w, out_b, init_h, out);
}

// round 7
// speedup vs baseline: 2.6367x; 2.6367x over previous
#include <cuda_runtime.h>
#include <cuda_bf16.h>
#include <cstdint>

#define NCELL 65536
#define TST   365

// smem byte offsets
#define HHI 0          // h_hi: 128 rows x 144B (64 bf16 + pad)   = 18432
#define HLO 18432      // h_lo: same                               = 18432
#define XB  36864      // x block: 128 rows x 48B                  =  6144
#define PT  43008      // pt double buffer: 2 x 128 x float2       =  2048
#define YPT 45056      // y partials: 8 x 128 x f32                =  4096
#define SMB 49152

typedef unsigned int u32;
typedef unsigned short u16;

static __device__ __forceinline__ u32 s2u(const void* p) {
    u32 a;
    asm("{ .reg .u64 t; cvta.to.shared.u64 t, %1; cvt.u32.u64 %0, t; }"
        : "=r"(a) : "l"(p));
    return a;
}
static __device__ __forceinline__ float bf2f(u16 b) {
    return __uint_as_float(((u32)b) << 16);
}
static __device__ __forceinline__ u16 f2bf(float f) {
    return __bfloat16_as_ushort(__float2bfloat16(f));
}
static __device__ __forceinline__ u32 pk(u16 a, u16 b) {
    return (u32)a | ((u32)b << 16);
}
static __device__ __forceinline__ float sigm(float x) {
    float e = __expf(-x);
    float r;
    asm("rcp.approx.f32 %0, %1;" : "=f"(r) : "f"(1.0f + e));
    return r;
}
static __device__ __forceinline__ float tanhv(float x) {
    return fmaf(2.0f, sigm(2.0f * x), -1.0f);
}

#define LDSM4(R, ad) \
    asm volatile("ldmatrix.sync.aligned.m8n8.x4.shared.b16 {%0,%1,%2,%3}, [%4];" \
        : "=r"((R)[0]), "=r"((R)[1]), "=r"((R)[2]), "=r"((R)[3]) : "r"(ad) : "memory")

#define HMMA(D, A, B0, B1) \
    asm("mma.sync.aligned.m16n8k16.row.col.f32.bf16.bf16.f32 " \
        "{%0,%1,%2,%3}, {%4,%5,%6,%7}, {%8,%9}, {%0,%1,%2,%3};" \
        : "+f"((D)[0]), "+f"((D)[1]), "+f"((D)[2]), "+f"((D)[3]) \
        : "r"((A)[0]), "r"((A)[1]), "r"((A)[2]), "r"((A)[3]), "r"(B0), "r"(B1))

__global__ void __launch_bounds__(256, 1)
gru_mma_kernel(const float* __restrict__ precip, const float* __restrict__ temp,
               const float* __restrict__ w_ih, const float* __restrict__ w_hh,
               const float* __restrict__ bias, const float* __restrict__ bias_n,
               const float* __restrict__ out_w, const float* __restrict__ out_b,
               const float* __restrict__ init_h, float* __restrict__ out) {
    extern __shared__ char sm[];
    const u32 sb = s2u(sm);
    u16* hhi16 = (u16*)(sm + HHI);
    u16* hlo16 = (u16*)(sm + HLO);
    float2* ptb = (float2*)(sm + PT);
    float* ypart = (float*)(sm + YPT);

    const int tid  = threadIdx.x;
    const int wid  = tid >> 5;
    const int lane = tid & 31;
    const int g    = lane >> 2;
    const int c4   = lane & 3;
    const int k0   = 8 * wid + 2 * c4;     // this thread's hidden-index pair base
    const int cellbase = blockIdx.x * 128;

    // ---------- resident B fragments (built once from gmem) ----------
    // Bh/Bl[grp][kchunk][rr]: Whh hi/lo; grp 0=r,1=z,2=n. Bx[grp][2]: x-chunk (r,z).
    u32 Bh[3][4][2], Bl[3][4][2], Bx[2][2];
#pragma unroll
    for (int grp = 0; grp < 3; ++grp) {
        const int gate = grp * 64 + 8 * wid + g;   // B col (n) = gate
        const float* wr = w_hh + gate * 64;
#pragma unroll
        for (int c = 0; c < 4; ++c) {
#pragma unroll
            for (int rr = 0; rr < 2; ++rr) {
                int kk = c * 16 + rr * 8 + 2 * c4;
                float w0 = wr[kk], w1 = wr[kk + 1];
                u16 h0 = f2bf(w0), h1 = f2bf(w1);
                Bh[grp][c][rr] = pk(h0, h1);
                Bl[grp][c][rr] = pk(f2bf(w0 - bf2f(h0)), f2bf(w1 - bf2f(h1)));
            }
        }
    }
#pragma unroll
    for (int grp = 0; grp < 2; ++grp) {
        const int gate = grp * 64 + 8 * wid + g;
        float w0 = w_ih[gate * 2], w1 = w_ih[gate * 2 + 1], bb = bias[gate];
        u16 w0h = f2bf(w0), w1h = f2bf(w1), bh = f2bf(bb);
        u32 v;
        if (c4 <= 1)      v = pk(w0h, w1h);                 // k rows 0,1 / 2,3: w_hi
        else if (c4 == 2) v = pk(f2bf(w0 - bf2f(w0h)),      // k rows 4,5: w_lo
                                 f2bf(w1 - bf2f(w1h)));
        else              v = pk(bh, f2bf(bb - bf2f(bh)));  // k rows 6,7: bias hi/lo
        Bx[grp][0] = v;
        Bx[grp][1] = 0;                                     // k rows 8-15 unused
    }

    // exact fp32 scalar constants: candidate-gate x-part, bias_n, out_w
    const float wp0 = w_ih[(128 + k0) * 2],     wt0 = w_ih[(128 + k0) * 2 + 1];
    const float wp1 = w_ih[(128 + k0 + 1) * 2], wt1 = w_ih[(128 + k0 + 1) * 2 + 1];
    const float bb0 = bias[128 + k0], bb1 = bias[128 + k0 + 1];
    const float bn0 = bias_n[k0],     bn1 = bias_n[k0 + 1];
    const float ow0 = out_w[k0],      ow1 = out_w[k0 + 1];
    const float ob  = out_b[0];

    // ---------- init h smem (bf16 split of init_h, all cells) ----------
    for (int idx = tid; idx < 8192; idx += 256) {
        int cl = idx >> 6, k = idx & 63;
        float v = init_h[k];
        u16 hi = f2bf(v);
        hhi16[cl * 72 + k] = hi;
        hlo16[cl * 72 + k] = f2bf(v - bf2f(hi));
    }
    // ---------- init x block (t=0) + pt buffer 0; prefetch t=1 ----------
    float pv = 0.f, tv = 0.f;
    if (tid < 128) {
        float p0 = precip[cellbase + tid], t0 = temp[cellbase + tid];
        u16 ph = f2bf(p0), th = f2bf(t0);
        u16 pl = f2bf(p0 - bf2f(ph)), tl = f2bf(t0 - bf2f(th));
        u32* xr = (u32*)(sm + XB + tid * 48);
        xr[0] = pk(ph, th); xr[1] = pk(pl, tl);
        xr[2] = pk(ph, th); xr[3] = pk(0x3F80, 0x3F80);   // cols 6,7 = 1.0
        xr[4] = 0; xr[5] = 0; xr[6] = 0; xr[7] = 0;       // cols 8-15 = 0
        ptb[tid] = make_float2(p0, t0);
        pv = precip[NCELL + cellbase + tid];
        tv = temp[NCELL + cellbase + tid];
    }
    __syncthreads();

    // ldmatrix per-lane address offsets
    const u32 lmoff = (u32)((lane & 15) * 144 + (lane >> 4) * 16);
    const u32 xlm   = (u32)((lane & 15) * 48  + (lane >> 4) * 16);
    const u32 ahi_b = sb + HHI + lmoff;
    const u32 alo_b = sb + HLO + lmoff;
    const u32 ax_b  = sb + XB  + xlm;

    for (int t = 0; t < TST; ++t) {
        float d[8][3][4];
#pragma unroll
        for (int mt = 0; mt < 8; ++mt)
#pragma unroll
            for (int gr = 0; gr < 3; ++gr)
#pragma unroll
                for (int q = 0; q < 4; ++q) d[mt][gr][q] = 0.f;

        // h_hi chunks: x Whi (main) and x Wlo (weight low bits)
#pragma unroll
        for (int c = 0; c < 4; ++c) {
            u32 a[8][4];
#pragma unroll
            for (int mt = 0; mt < 8; ++mt)
                LDSM4(a[mt], ahi_b + mt * 2304 + c * 32);
#pragma unroll
            for (int mt = 0; mt < 8; ++mt) {
                HMMA(d[mt][0], a[mt], Bh[0][c][0], Bh[0][c][1]);
                HMMA(d[mt][1], a[mt], Bh[1][c][0], Bh[1][c][1]);
                HMMA(d[mt][2], a[mt], Bh[2][c][0], Bh[2][c][1]);
                HMMA(d[mt][0], a[mt], Bl[0][c][0], Bl[0][c][1]);
                HMMA(d[mt][1], a[mt], Bl[1][c][0], Bl[1][c][1]);
                HMMA(d[mt][2], a[mt], Bl[2][c][0], Bl[2][c][1]);
            }
        }
        // h_lo chunks: x Whi
#pragma unroll
        for (int c = 0; c < 4; ++c) {
            u32 a[8][4];
#pragma unroll
            for (int mt = 0; mt < 8; ++mt)
                LDSM4(a[mt], alo_b + mt * 2304 + c * 32);
#pragma unroll
            for (int mt = 0; mt < 8; ++mt) {
                HMMA(d[mt][0], a[mt], Bh[0][c][0], Bh[0][c][1]);
                HMMA(d[mt][1], a[mt], Bh[1][c][0], Bh[1][c][1]);
                HMMA(d[mt][2], a[mt], Bh[2][c][0], Bh[2][c][1]);
            }
        }
        // x chunk (r and z groups only)
#pragma unroll
        for (int mt = 0; mt < 8; ++mt) {
            u32 ax[4];
            LDSM4(ax, ax_b + mt * 768);
            HMMA(d[mt][0], ax, Bx[0][0], Bx[0][1]);
            HMMA(d[mt][1], ax, Bx[1][0], Bx[1][1]);
        }

        __syncthreads();   // #1: all smem reads of h/x for step t complete

        // writers: stage x block + pt for step t+1; prefetch t+2
        if (tid < 128) {
            u16 ph = f2bf(pv), th = f2bf(tv);
            u16 pl = f2bf(pv - bf2f(ph)), tl = f2bf(tv - bf2f(th));
            u32* xr = (u32*)(sm + XB + tid * 48);
            xr[0] = pk(ph, th); xr[1] = pk(pl, tl);
            xr[2] = pk(ph, th); xr[3] = pk(0x3F80, 0x3F80);
            ptb[((t + 1) & 1) * 128 + tid] = make_float2(pv, tv);
            int tn = (t + 2 < TST) ? t + 2 : TST - 1;
            pv = precip[tn * NCELL + cellbase + tid];
            tv = temp[tn * NCELL + cellbase + tid];
        }

        // ---------- epilogue: gates, h update, y partials ----------
        const float2* ptc = ptb + (t & 1) * 128;
#pragma unroll
        for (int mt = 0; mt < 8; ++mt) {
#pragma unroll
            for (int half = 0; half < 2; ++half) {
                const int cell = mt * 16 + g + half * 8;
                float2 xv = ptc[cell];
                u32 hw = *(u32*)&hhi16[cell * 72 + k0];
                u32 lw = *(u32*)&hlo16[cell * 72 + k0];
                float ho0 = bf2f((u16)hw)         + bf2f((u16)lw);
                float ho1 = bf2f((u16)(hw >> 16)) + bf2f((u16)(lw >> 16));
                float Dr0 = d[mt][0][2 * half + 0], Dr1 = d[mt][0][2 * half + 1];
                float Dz0 = d[mt][1][2 * half + 0], Dz1 = d[mt][1][2 * half + 1];
                float Dn0 = d[mt][2][2 * half + 0], Dn1 = d[mt][2][2 * half + 1];
                float r0 = sigm(Dr0), r1 = sigm(Dr1);
                float z0 = sigm(Dz0), z1 = sigm(Dz1);
                float in0 = fmaf(wp0, xv.x, fmaf(wt0, xv.y, bb0));
                float in1 = fmaf(wp1, xv.x, fmaf(wt1, xv.y, bb1));
                float n0 = tanhv(fmaf(r0, Dn0 + bn0, in0));
                float n1 = tanhv(fmaf(r1, Dn1 + bn1, in1));
                float h0 = fmaf(z0, ho0 - n0, n0);   // new + z*(h_old - new)
                float h1 = fmaf(z1, ho1 - n1, n1);
                u16 h0h = f2bf(h0), h1h = f2bf(h1);
                *(u32*)&hhi16[cell * 72 + k0] = pk(h0h, h1h);
                *(u32*)&hlo16[cell * 72 + k0] =
                    pk(f2bf(h0 - bf2f(h0h)), f2bf(h1 - bf2f(h1h)));
                float yq = fmaf(ow0, h0, ow1 * h1);
                yq += __shfl_xor_sync(0xffffffffu, yq, 1);
                yq += __shfl_xor_sync(0xffffffffu, yq, 2);
                if (c4 == 0) ypart[wid * 128 + cell] = yq;
            }
        }
        __syncthreads();   // #2: h/x/ypart writes visible

        if (tid < 128) {
            float y = ob;
#pragma unroll
            for (int w = 0; w < 8; ++w) y += ypart[w * 128 + tid];
            out[t * NCELL + cellbase + tid] = y;
        }
    }

    // ---------- final hidden state ----------
    for (int idx = tid; idx < 8192; idx += 256) {
        int cl = idx >> 6, k = idx & 63;
        float v = bf2f(hhi16[cl * 72 + k]) + bf2f(hlo16[cl * 72 + k]);
        out[(long long)TST * NCELL + (long long)(cellbase + cl) * 64 + k] = v;
    }
}

extern "C" void kernel_launch(void* const* d_in, const int* in_sizes, int n_in,
                              void* d_out, int out_size) {
    const float* precip = (const float*)d_in[0];
    const float* temp   = (const float*)d_in[1];
    const float* w_ih   = (const float*)d_in[2];
    const float* w_hh   = (const float*)d_in[3];
    const float* bias   = (const float*)d_in[4];
    const float* bias_n = (const float*)d_in[5];
    const float* out_w  = (const float*)d_in[6];
    const float* out_b  = (const float*)d_in[7];
    const float* init_h = (const float*)d_in[8];
    float* out = (float*)d_out;

    cudaFuncSetAttribute(gru_mma_kernel,
                         cudaFuncAttributeMaxDynamicSharedMemorySize, SMB);
    gru_mma_kernel<<<NCELL / 128, 256, SMB>>>(
        precip, temp, w_ih, w_hh, bias, bias_n, out_w, out_b, init_h, out);
}